// round 1
// baseline (speedup 1.0000x reference)
#include <cuda_runtime.h>
#include <math.h>

#define BB   4
#define LL   1024
#define DD   256
#define HH   8
#define DKK  32
#define INV_TEMP 0.08838834764831845f   /* 1/sqrt(4*32) */
#define NEGV (-1e9f)
#define EPSV (1e-6f)

/* ------------------------------------------------------------------ */
/* scratch (static device globals: allocation-guard safe)              */
/* ------------------------------------------------------------------ */
__device__ float g_Q [BB*LL*DD];   /* [b,l,h,dk] == [4096][256] */
__device__ float g_K [BB*LL*DD];
__device__ float g_V [BB*LL*DD];
__device__ float g_OH[BB*LL*DD];   /* attn @ V, [b,l,h,dv]       */
__device__ float g_attn_fb[(size_t)BB*HH*LL*LL]; /* fallback if attn not in d_out */

/* ------------------------------------------------------------------ */
/* GEMM: Y[4096,256] = Xa@Wa + Xs@Ws  (two K=256 inputs, K_eff=512)   */
/* BM=64 BN=64 BK=16, 256 thr, 4x4 micro-tile                          */
/* ------------------------------------------------------------------ */
__global__ void proj_kernel(const float* __restrict__ Xa, const float* __restrict__ Wa,
                            const float* __restrict__ Xs, const float* __restrict__ Ws,
                            float* __restrict__ Y)
{
    __shared__ float As[16][68];   /* [k][m], padded */
    __shared__ float Bs[16][64];   /* [k][n] */

    const int tid  = threadIdx.x;
    const int tx   = tid & 15, ty = tid >> 4;
    const int row0 = blockIdx.y * 64;
    const int col0 = blockIdx.x * 64;

    const int lr = tid >> 2;            /* A load row 0..63   */
    const int lc = (tid & 3) << 2;      /* A load k   0,4,8,12 */
    const int bk = tid >> 4;            /* B load k row 0..15  */
    const int bc = (tid & 15) << 2;     /* B load col          */

    float acc[4][4];
#pragma unroll
    for (int i = 0; i < 4; i++)
#pragma unroll
        for (int j = 0; j < 4; j++) acc[i][j] = 0.f;

    for (int kt = 0; kt < 512; kt += 16) {
        const float* Xp; const float* Wp; int kk0;
        if (kt < 256) { Xp = Xa; Wp = Wa; kk0 = kt; }
        else          { Xp = Xs; Wp = Ws; kk0 = kt - 256; }

        float4 av = *(const float4*)&Xp[(size_t)(row0 + lr) * 256 + kk0 + lc];
        As[lc + 0][lr] = av.x; As[lc + 1][lr] = av.y;
        As[lc + 2][lr] = av.z; As[lc + 3][lr] = av.w;
        *(float4*)&Bs[bk][bc] = *(const float4*)&Wp[(size_t)(kk0 + bk) * 256 + col0 + bc];
        __syncthreads();

#pragma unroll
        for (int k = 0; k < 16; k++) {
            float4 a = *(float4*)&As[k][ty << 2];
            float4 b = *(float4*)&Bs[k][tx << 2];
            acc[0][0] += a.x*b.x; acc[0][1] += a.x*b.y; acc[0][2] += a.x*b.z; acc[0][3] += a.x*b.w;
            acc[1][0] += a.y*b.x; acc[1][1] += a.y*b.y; acc[1][2] += a.y*b.z; acc[1][3] += a.y*b.w;
            acc[2][0] += a.z*b.x; acc[2][1] += a.z*b.y; acc[2][2] += a.z*b.z; acc[2][3] += a.z*b.w;
            acc[3][0] += a.w*b.x; acc[3][1] += a.w*b.y; acc[3][2] += a.w*b.z; acc[3][3] += a.w*b.w;
        }
        __syncthreads();
    }

#pragma unroll
    for (int r = 0; r < 4; r++) {
        float4 o = make_float4(acc[r][0], acc[r][1], acc[r][2], acc[r][3]);
        *(float4*)&Y[(size_t)(row0 + (ty << 2) + r) * 256 + col0 + (tx << 2)] = o;
    }
}

/* ------------------------------------------------------------------ */
/* FC: Y = X@W + (7-way residual).  Same tiling, K=256.                */
/* ------------------------------------------------------------------ */
__global__ void fc_kernel(const float* __restrict__ X, const float* __restrict__ W,
                          const float* __restrict__ r0, const float* __restrict__ r1,
                          const float* __restrict__ r2, const float* __restrict__ r3,
                          const float* __restrict__ r4, const float* __restrict__ r5,
                          const float* __restrict__ r6, float* __restrict__ Y)
{
    __shared__ float As[16][68];
    __shared__ float Bs[16][64];

    const int tid  = threadIdx.x;
    const int tx   = tid & 15, ty = tid >> 4;
    const int row0 = blockIdx.y * 64;
    const int col0 = blockIdx.x * 64;

    const int lr = tid >> 2;
    const int lc = (tid & 3) << 2;
    const int bk = tid >> 4;
    const int bc = (tid & 15) << 2;

    float acc[4][4];
#pragma unroll
    for (int i = 0; i < 4; i++)
#pragma unroll
        for (int j = 0; j < 4; j++) acc[i][j] = 0.f;

    for (int kt = 0; kt < 256; kt += 16) {
        float4 av = *(const float4*)&X[(size_t)(row0 + lr) * 256 + kt + lc];
        As[lc + 0][lr] = av.x; As[lc + 1][lr] = av.y;
        As[lc + 2][lr] = av.z; As[lc + 3][lr] = av.w;
        *(float4*)&Bs[bk][bc] = *(const float4*)&W[(size_t)(kt + bk) * 256 + col0 + bc];
        __syncthreads();

#pragma unroll
        for (int k = 0; k < 16; k++) {
            float4 a = *(float4*)&As[k][ty << 2];
            float4 b = *(float4*)&Bs[k][tx << 2];
            acc[0][0] += a.x*b.x; acc[0][1] += a.x*b.y; acc[0][2] += a.x*b.z; acc[0][3] += a.x*b.w;
            acc[1][0] += a.y*b.x; acc[1][1] += a.y*b.y; acc[1][2] += a.y*b.z; acc[1][3] += a.y*b.w;
            acc[2][0] += a.z*b.x; acc[2][1] += a.z*b.y; acc[2][2] += a.z*b.z; acc[2][3] += a.z*b.w;
            acc[3][0] += a.w*b.x; acc[3][1] += a.w*b.y; acc[3][2] += a.w*b.z; acc[3][3] += a.w*b.w;
        }
        __syncthreads();
    }

#pragma unroll
    for (int r = 0; r < 4; r++) {
        size_t idx = (size_t)(row0 + (ty << 2) + r) * 256 + col0 + (tx << 2);
        float4 o = make_float4(acc[r][0], acc[r][1], acc[r][2], acc[r][3]);
        float4 t;
        t = *(const float4*)&r0[idx]; o.x += t.x; o.y += t.y; o.z += t.z; o.w += t.w;
        t = *(const float4*)&r1[idx]; o.x += t.x; o.y += t.y; o.z += t.z; o.w += t.w;
        t = *(const float4*)&r2[idx]; o.x += t.x; o.y += t.y; o.z += t.z; o.w += t.w;
        t = *(const float4*)&r3[idx]; o.x += t.x; o.y += t.y; o.z += t.z; o.w += t.w;
        t = *(const float4*)&r4[idx]; o.x += t.x; o.y += t.y; o.z += t.z; o.w += t.w;
        t = *(const float4*)&r5[idx]; o.x += t.x; o.y += t.y; o.z += t.z; o.w += t.w;
        t = *(const float4*)&r6[idx]; o.x += t.x; o.y += t.y; o.z += t.z; o.w += t.w;
        *(float4*)&Y[idx] = o;
    }
}

/* ------------------------------------------------------------------ */
/* Attention. Block = (bh, 32 q-rows), 256 thr (8 warps x 32 lanes).   */
/* Warp w owns q rows w*4..w*4+3; lane spans k.                        */
/* Pass 1: scores -> raw masked scores into attn buffer + online (m,s).*/
/* Pass 2: re-read scores, softmax in place, accumulate attn@V.        */
/* ------------------------------------------------------------------ */
__global__ void attn_kernel(const float* __restrict__ Q, const float* __restrict__ K,
                            const float* __restrict__ V, const int* __restrict__ mask,
                            float* __restrict__ attn, float* __restrict__ OH)
{
    const int bh = blockIdx.y;
    const int b  = bh >> 3, h = bh & 7;
    const int q0 = blockIdx.x * 32;
    const int tid  = threadIdx.x;
    const int w    = tid >> 5, lane = tid & 31;

    __shared__ float Qs [32][33];
    __shared__ float KVs[128][33];

    {
        int r = tid >> 3, c = (tid & 7) << 2;
        float4 v4 = *(const float4*)&Q[((size_t)(b * LL + q0 + r) * HH + h) * DKK + c];
        Qs[r][c] = v4.x; Qs[r][c+1] = v4.y; Qs[r][c+2] = v4.z; Qs[r][c+3] = v4.w;
    }

    float m[4], s[4];
#pragma unroll
    for (int r = 0; r < 4; r++) { m[r] = -3.0e38f; s[r] = 0.f; }

    float* abase = attn + ((size_t)bh * LL + q0) * LL;

    /* ---------- PASS 1: scores + online stats ---------- */
    for (int kt = 0; kt < LL; kt += 128) {
        __syncthreads();
#pragma unroll
        for (int it = 0; it < 4; it++) {
            int fi = tid + it * 256;
            int r = fi >> 3, c = (fi & 7) << 2;
            float4 v4 = *(const float4*)&K[((size_t)(b * LL + kt + r) * HH + h) * DKK + c];
            KVs[r][c] = v4.x; KVs[r][c+1] = v4.y; KVs[r][c+2] = v4.z; KVs[r][c+3] = v4.w;
        }
        __syncthreads();

        float sc[4][4];
#pragma unroll
        for (int r = 0; r < 4; r++)
#pragma unroll
            for (int j = 0; j < 4; j++) sc[r][j] = 0.f;

#pragma unroll
        for (int d = 0; d < 32; d++) {
            float k0 = KVs[lane      ][d];
            float k1 = KVs[lane + 32 ][d];
            float k2 = KVs[lane + 64 ][d];
            float k3 = KVs[lane + 96 ][d];
#pragma unroll
            for (int r = 0; r < 4; r++) {
                float qv = Qs[(w << 2) + r][d];
                sc[r][0] += qv * k0; sc[r][1] += qv * k1;
                sc[r][2] += qv * k2; sc[r][3] += qv * k3;
            }
        }

#pragma unroll
        for (int r = 0; r < 4; r++) {
            int q = q0 + (w << 2) + r;
            const int* mp = mask + ((size_t)b * LL + q) * LL + kt;
            float*     ap = abase + (size_t)((w << 2) + r) * LL + kt;
#pragma unroll
            for (int j = 0; j < 4; j++) {
                int k = lane + j * 32;
                float v = sc[r][j] * INV_TEMP;
                if (mp[k] == 0) v = NEGV;
                ap[k] = v;
                float nm = fmaxf(m[r], v);
                s[r] = s[r] * __expf(m[r] - nm) + __expf(v - nm);
                m[r] = nm;
            }
        }
    }

    /* merge (m,s) across lanes */
#pragma unroll
    for (int off = 16; off; off >>= 1) {
#pragma unroll
        for (int r = 0; r < 4; r++) {
            float m2 = __shfl_xor_sync(0xffffffffu, m[r], off);
            float s2 = __shfl_xor_sync(0xffffffffu, s[r], off);
            float nm = fmaxf(m[r], m2);
            s[r] = s[r] * __expf(m[r] - nm) + s2 * __expf(m2 - nm);
            m[r] = nm;
        }
    }
    float inv_s[4];
#pragma unroll
    for (int r = 0; r < 4; r++) inv_s[r] = 1.f / s[r];

    /* ---------- PASS 2: softmax in place + attn@V ---------- */
    float oacc[4] = {0.f, 0.f, 0.f, 0.f};   /* dv = lane */
    for (int kt = 0; kt < LL; kt += 128) {
        __syncthreads();
#pragma unroll
        for (int it = 0; it < 4; it++) {
            int fi = tid + it * 256;
            int r = fi >> 3, c = (fi & 7) << 2;
            float4 v4 = *(const float4*)&V[((size_t)(b * LL + kt + r) * HH + h) * DKK + c];
            KVs[r][c] = v4.x; KVs[r][c+1] = v4.y; KVs[r][c+2] = v4.z; KVs[r][c+3] = v4.w;
        }
        __syncthreads();

        float p[4][4];
#pragma unroll
        for (int r = 0; r < 4; r++) {
            float* ap = abase + (size_t)((w << 2) + r) * LL + kt;
#pragma unroll
            for (int j = 0; j < 4; j++) {
                float v  = ap[lane + j * 32];
                float pv = __expf(v - m[r]) * inv_s[r];
                p[r][j] = pv;
                ap[lane + j * 32] = pv;
            }
        }

#pragma unroll
        for (int j = 0; j < 4; j++) {
#pragma unroll 8
            for (int kk = 0; kk < 32; kk++) {
                float vv = KVs[j * 32 + kk][lane];
                oacc[0] += __shfl_sync(0xffffffffu, p[0][j], kk) * vv;
                oacc[1] += __shfl_sync(0xffffffffu, p[1][j], kk) * vv;
                oacc[2] += __shfl_sync(0xffffffffu, p[2][j], kk) * vv;
                oacc[3] += __shfl_sync(0xffffffffu, p[3][j], kk) * vv;
            }
        }
    }

#pragma unroll
    for (int r = 0; r < 4; r++)
        OH[((size_t)(b * LL + q0 + (w << 2) + r) * HH + h) * DKK + lane] = oacc[r];
}

/* ------------------------------------------------------------------ */
/* LayerNorm in place, one block per row                               */
/* ------------------------------------------------------------------ */
__global__ void ln_kernel(float* __restrict__ io,
                          const float* __restrict__ g, const float* __restrict__ bta)
{
    const int row = blockIdx.x;
    const int t   = threadIdx.x;
    __shared__ float red[256];

    float v = io[(size_t)row * DD + t];
    red[t] = v;
    __syncthreads();
#pragma unroll
    for (int off = 128; off > 0; off >>= 1) {
        if (t < off) red[t] += red[t + off];
        __syncthreads();
    }
    float mu = red[0] * (1.0f / DD);
    __syncthreads();

    float d = v - mu;
    red[t] = d * d;
    __syncthreads();
#pragma unroll
    for (int off = 128; off > 0; off >>= 1) {
        if (t < off) red[t] += red[t + off];
        __syncthreads();
    }
    float var = red[0] * (1.0f / DD);

    io[(size_t)row * DD + t] = d * rsqrtf(var + EPSV) * g[t] + bta[t];
}

/* ------------------------------------------------------------------ */
extern "C" void kernel_launch(void* const* d_in, const int* in_sizes, int n_in,
                              void* d_out, int out_size)
{
    const float* q_a  = (const float*)d_in[0];
    const float* k_a  = (const float*)d_in[1];
    const float* v_a  = (const float*)d_in[2];
    const float* q_s  = (const float*)d_in[3];
    const float* k_s  = (const float*)d_in[4];
    const float* v_s  = (const float*)d_in[5];
    const float* q_bh = (const float*)d_in[6];
    const float* q_bah= (const float*)d_in[7];
    const float* q_bbh= (const float*)d_in[8];
    const float* q_pan= (const float*)d_in[9];
    const float* q_oan= (const float*)d_in[10];
    const int*   mask = (const int*)  d_in[11];
    const float* w_qa = (const float*)d_in[12];
    const float* w_ka = (const float*)d_in[13];
    const float* w_va = (const float*)d_in[14];
    const float* w_qs = (const float*)d_in[15];
    const float* w_ks = (const float*)d_in[16];
    const float* w_vs = (const float*)d_in[17];
    const float* w_fc = (const float*)d_in[18];
    const float* ln_g = (const float*)d_in[19];
    const float* ln_b = (const float*)d_in[20];
    (void)in_sizes; (void)n_in;

    float *Qp, *Kp, *Vp, *OHp, *attn_fb;
    cudaGetSymbolAddress((void**)&Qp,  g_Q);
    cudaGetSymbolAddress((void**)&Kp,  g_K);
    cudaGetSymbolAddress((void**)&Vp,  g_V);
    cudaGetSymbolAddress((void**)&OHp, g_OH);
    cudaGetSymbolAddress((void**)&attn_fb, g_attn_fb);

    float* out = (float*)d_out;
    const size_t outN  = (size_t)BB * LL * DD;
    const size_t attnN = (size_t)BB * HH * LL * LL;
    float* attn = ((size_t)out_size >= outN + attnN) ? (out + outN) : attn_fb;

    dim3 gemmGrid(DD / 64, (BB * LL) / 64);
    proj_kernel<<<gemmGrid, 256>>>(q_a, w_qa, q_s, w_qs, Qp);
    proj_kernel<<<gemmGrid, 256>>>(k_a, w_ka, k_s, w_ks, Kp);
    proj_kernel<<<gemmGrid, 256>>>(v_a, w_va, v_s, w_vs, Vp);

    attn_kernel<<<dim3(LL / 32, BB * HH), 256>>>(Qp, Kp, Vp, mask, attn, OHp);

    fc_kernel<<<gemmGrid, 256>>>(OHp, w_fc,
                                 q_a, q_s, q_bh, q_bah, q_bbh, q_pan, q_oan, out);

    ln_kernel<<<BB * LL, 256>>>(out, ln_g, ln_b);
}